// round 1
// baseline (speedup 1.0000x reference)
#include <cuda_runtime.h>

// TSM temporal shift: x shape (bt=128, c=96, h=56, w=56), N_FRAME=8, fold=32.
// out[b,t,c]   = x[b,t+1,c]  for c in [0,32)   (zero at t=7)
// out[b,t,c]   = x[b,t-1,c]  for c in [32,64)  (zero at t=0)
// out[b,t,c]   = x[b,t,c]    for c in [64,96)
//
// Pure bandwidth problem. One CTA per (bt,c) plane; plane = 3136 floats = 784 float4.

#define C_DIM    96
#define N_FRAME  8
#define FOLD     32
#define HW4      784   // 56*56/4

__global__ __launch_bounds__(256) void tsm_shift_kernel(
    const float4* __restrict__ x, float4* __restrict__ out)
{
    const int plane = blockIdx.x;          // bt * 96 + c
    const int c  = plane % C_DIM;
    const int bt = plane / C_DIM;
    const int t  = bt % N_FRAME;

    const float4* src;
    bool zero = false;
    if (c < FOLD) {
        // shift left in time: read t+1
        if (t < N_FRAME - 1) src = x + (size_t)(plane + C_DIM) * HW4;
        else { zero = true; src = x; }
    } else if (c < 2 * FOLD) {
        // shift right in time: read t-1
        if (t > 0) src = x + (size_t)(plane - C_DIM) * HW4;
        else { zero = true; src = x; }
    } else {
        src = x + (size_t)plane * HW4;
    }

    float4* dst = out + (size_t)plane * HW4;
    const int tid = threadIdx.x;

    if (!zero) {
        // 784 = 3*256 + 16 -> 4 iterations, last mostly predicated off.
        #pragma unroll 4
        for (int i = tid; i < HW4; i += 256) {
            dst[i] = src[i];
        }
    } else {
        const float4 z = make_float4(0.f, 0.f, 0.f, 0.f);
        #pragma unroll 4
        for (int i = tid; i < HW4; i += 256) {
            dst[i] = z;
        }
    }
}

extern "C" void kernel_launch(void* const* d_in, const int* in_sizes, int n_in,
                              void* d_out, int out_size)
{
    const float4* x = (const float4*)d_in[0];
    float4* out = (float4*)d_out;
    // 128 * 96 = 12288 planes
    tsm_shift_kernel<<<12288, 256>>>(x, out);
}

// round 2
// speedup vs baseline: 1.0733x; 1.0733x over previous
#include <cuda_runtime.h>

// TSM temporal shift: x shape (bt=128, c=96, h=56, w=56), N_FRAME=8, fold=32.
// out[b,t,c] = x[b,t+1,c] for c in [0,32)   (zero at t=7)
// out[b,t,c] = x[b,t-1,c] for c in [32,64)  (zero at t=0)
// out[b,t,c] = x[b,t,c]   for c in [64,96)
//
// Pure bandwidth. One CTA per (bt,c) plane; plane = 3136 floats = 784 float4.
// R2: front-batched loads (MLP=4, no STG between LDGs) + streaming cache
// hints (.cs) since the 295MB working set streams through the 126MB L2.

#define C_DIM    96
#define N_FRAME  8
#define FOLD     32
#define HW4      784   // 56*56/4

__global__ __launch_bounds__(256) void tsm_shift_kernel(
    const float4* __restrict__ x, float4* __restrict__ out)
{
    const int plane = blockIdx.x;          // bt * 96 + c
    const int c  = plane % C_DIM;
    const int bt = plane / C_DIM;
    const int t  = bt % N_FRAME;

    const float4* src = x + (size_t)plane * HW4;
    bool zero = false;
    if (c < FOLD) {
        if (t < N_FRAME - 1) src += (size_t)C_DIM * HW4;   // read t+1
        else zero = true;
    } else if (c < 2 * FOLD) {
        if (t > 0) src -= (size_t)C_DIM * HW4;             // read t-1
        else zero = true;
    }

    float4* dst = out + (size_t)plane * HW4;
    const int tid = threadIdx.x;
    const bool tail = (tid < HW4 - 3 * 256);               // tid < 16

    if (!zero) {
        // Batch all loads first (4 independent LDG.128.CS), then store.
        float4 v0 = __ldcs(src + tid);
        float4 v1 = __ldcs(src + tid + 256);
        float4 v2 = __ldcs(src + tid + 512);
        float4 v3;
        if (tail) v3 = __ldcs(src + tid + 768);
        __stcs(dst + tid,       v0);
        __stcs(dst + tid + 256, v1);
        __stcs(dst + tid + 512, v2);
        if (tail) __stcs(dst + tid + 768, v3);
    } else {
        const float4 z = make_float4(0.f, 0.f, 0.f, 0.f);
        __stcs(dst + tid,       z);
        __stcs(dst + tid + 256, z);
        __stcs(dst + tid + 512, z);
        if (tail) __stcs(dst + tid + 768, z);
    }
}

extern "C" void kernel_launch(void* const* d_in, const int* in_sizes, int n_in,
                              void* d_out, int out_size)
{
    const float4* x = (const float4*)d_in[0];
    float4* out = (float4*)d_out;
    tsm_shift_kernel<<<12288, 256>>>(x, out);  // 128*96 planes
}